// round 17
// baseline (speedup 1.0000x reference)
#include <cuda_runtime.h>

#define BATCH   8
#define SEQ     4096
#define DIM     64
#define DS      16
#define CHUNK   64
#define NCHUNK  (SEQ / CHUNK)        // 64
#define ROWS    (BATCH * SEQ)        // 32768
#define NSUPER  8                    // superchunks per batch
#define SCH     (NCHUNK / NSUPER)    // 8 chunks per superchunk

#define XST 72                        // X smem stride (perm cols), 72 % 32 == 8
#define WPA 136                       // W-pair stride, N=64 tiles (136 % 32 == 8)
#define WPB 264                       // W-pair stride, N=128 tiles (264 % 32 == 8)

// Scratch (device globals; no allocations allowed)
__device__ float g_A  [ROWS * 256];            // per-timestep A_t [row][i*16+l]
__device__ float g_Bx [ROWS * DS];             // per-timestep Bx_t
__device__ float g_P  [BATCH * NCHUNK * 256];  // per-chunk cumulative transition
__device__ float g_v  [BATCH * NCHUNK * DS];   // per-chunk aggregate input
__device__ float g_H  [ROWS * DS];             // h_t for every timestep
__device__ float g_SP [BATCH * NSUPER * 256];  // per-superchunk transition
__device__ float g_Sv [BATCH * NSUPER * DS];   // per-superchunk aggregate
__device__ float g_sh0[BATCH * NSUPER * DS];   // state entering each superchunk

// ---------------------------------------------------------------------------
// helpers
// ---------------------------------------------------------------------------
__device__ __forceinline__ float f2tf(float f) {
    unsigned u;
    asm("cvt.rna.tf32.f32 %0, %1;" : "=r"(u) : "f"(f));
    return __uint_as_float(u);
}
__device__ __forceinline__ void mma8(float* c,
                                     unsigned a0, unsigned a1, unsigned a2, unsigned a3,
                                     unsigned b0, unsigned b1) {
    asm volatile(
        "mma.sync.aligned.m16n8k8.row.col.f32.tf32.tf32.f32 "
        "{%0,%1,%2,%3},{%4,%5,%6,%7},{%8,%9},{%0,%1,%2,%3};"
        : "+f"(c[0]), "+f"(c[1]), "+f"(c[2]), "+f"(c[3])
        : "r"(a0), "r"(a1), "r"(a2), "r"(a3), "r"(b0), "r"(b1));
}
__device__ __forceinline__ unsigned fu(float f) { return __float_as_uint(f); }
// column permutation: (k, k+4) adjacent
__device__ __forceinline__ int pmk(int k) {
    return ((k >> 3) << 3) + ((k & 3) << 1) + ((k >> 2) & 1);
}

// ---------------------------------------------------------------------------
// Kernel 1a (tensor): A = X @ W_A + b_A   ([32768,64] @ [64,256])
// Paired smem layouts: one LDS.64 per fragment pair.
// ---------------------------------------------------------------------------
__global__ __launch_bounds__(256) void k_projA(const float* __restrict__ x,
                                               const float* __restrict__ W,
                                               const float* __restrict__ bias) {
    extern __shared__ float sm[];
    float* Xs = sm;                  // [128][XST] perm cols
    float* Wp = sm + 128 * XST;      // [32][WPA]  k-pair rows
    const int tid = threadIdx.x;
    const int m0 = blockIdx.x * 128;
    const int n0 = blockIdx.y * 64;

#pragma unroll
    for (int it = 0; it < 8; it++) {
        int i4 = it * 256 + tid;
        int row = i4 >> 4, c4 = (i4 & 15) * 4;
        float4 v = *(const float4*)&x[(long)(m0 + row) * 64 + c4];
        int base = row * XST + ((c4 >> 3) << 3) + ((c4 >> 2) & 1);
        Xs[base + 0] = f2tf(v.x);
        Xs[base + 2] = f2tf(v.y);
        Xs[base + 4] = f2tf(v.z);
        Xs[base + 6] = f2tf(v.w);
    }
#pragma unroll
    for (int it = 0; it < 4; it++) {
        int i4 = it * 256 + tid;
        int row = i4 >> 4, c4 = (i4 & 15) * 4;   // row = k, c4 = n
        float4 v = *(const float4*)&W[(long)row * 256 + n0 + c4];
        int kk = ((row >> 3) << 2) + (row & 3);
        int base = kk * WPA + c4 * 2 + ((row >> 2) & 1);
        Wp[base + 0] = f2tf(v.x);
        Wp[base + 2] = f2tf(v.y);
        Wp[base + 4] = f2tf(v.z);
        Wp[base + 6] = f2tf(v.w);
    }
    __syncthreads();

    const int wid = tid >> 5, lane = tid & 31;
    const int g = lane >> 2, tig = lane & 3;
    const int wm = wid & 3, wn = wid >> 2;
    const int mbase = wm * 32, nbase = wn * 32;

    float c[2][4][4];
#pragma unroll
    for (int mt = 0; mt < 2; mt++)
#pragma unroll
        for (int nt = 0; nt < 4; nt++)
#pragma unroll
            for (int j = 0; j < 4; j++) c[mt][nt][j] = 0.f;

#pragma unroll
    for (int ks = 0; ks < 8; ks++) {
        unsigned a[2][4];
#pragma unroll
        for (int mt = 0; mt < 2; mt++) {
            int r = mbase + mt * 16 + g;
            float2 ap = *(const float2*)&Xs[r * XST + ks * 8 + tig * 2];
            float2 aq = *(const float2*)&Xs[(r + 8) * XST + ks * 8 + tig * 2];
            a[mt][0] = fu(ap.x); a[mt][1] = fu(aq.x);
            a[mt][2] = fu(ap.y); a[mt][3] = fu(aq.y);
        }
        unsigned b[4][2];
#pragma unroll
        for (int nt = 0; nt < 4; nt++) {
            int n = nbase + nt * 8 + g;
            float2 bp = *(const float2*)&Wp[(ks * 4 + tig) * WPA + n * 2];
            b[nt][0] = fu(bp.x); b[nt][1] = fu(bp.y);
        }
#pragma unroll
        for (int mt = 0; mt < 2; mt++)
#pragma unroll
            for (int nt = 0; nt < 4; nt++)
                mma8(c[mt][nt], a[mt][0], a[mt][1], a[mt][2], a[mt][3],
                     b[nt][0], b[nt][1]);
    }

#pragma unroll
    for (int mt = 0; mt < 2; mt++)
#pragma unroll
        for (int nt = 0; nt < 4; nt++) {
            int row = m0 + mbase + mt * 16 + g;
            int col = n0 + nbase + nt * 8 + tig * 2;
            float b0 = bias[col], b1 = bias[col + 1];
            *(float2*)&g_A[(long)row * 256 + col] =
                make_float2(c[mt][nt][0] + b0, c[mt][nt][1] + b1);
            *(float2*)&g_A[(long)(row + 8) * 256 + col] =
                make_float2(c[mt][nt][2] + b0, c[mt][nt][3] + b1);
        }
}

// ---------------------------------------------------------------------------
// Kernel 1b (tensor): Bm = X @ W_B + b_B fused with Bx = Bm . x
// ---------------------------------------------------------------------------
__global__ __launch_bounds__(256) void k_projB(const float* __restrict__ x,
                                               const float* __restrict__ W,
                                               const float* __restrict__ bias) {
    extern __shared__ float sm[];
    float* Xs  = sm;                  // [128][XST] perm cols
    float* Wp  = sm + 128 * XST;      // [32][WPB]
    float* red = Wp + 32 * WPB;       // [128][4]
    const int tid = threadIdx.x;
    const int m0 = blockIdx.x * 128;
    const int n0 = blockIdx.y * 128;

#pragma unroll
    for (int it = 0; it < 8; it++) {
        int i4 = it * 256 + tid;
        int row = i4 >> 4, c4 = (i4 & 15) * 4;
        float4 v = *(const float4*)&x[(long)(m0 + row) * 64 + c4];
        int base = row * XST + ((c4 >> 3) << 3) + ((c4 >> 2) & 1);
        Xs[base + 0] = f2tf(v.x);
        Xs[base + 2] = f2tf(v.y);
        Xs[base + 4] = f2tf(v.z);
        Xs[base + 6] = f2tf(v.w);
    }
#pragma unroll
    for (int it = 0; it < 8; it++) {
        int i4 = it * 256 + tid;
        int row = i4 >> 5, c4 = (i4 & 31) * 4;   // row = k, c4 = n (0..127)
        float4 v = *(const float4*)&W[(long)row * 1024 + n0 + c4];
        int kk = ((row >> 3) << 2) + (row & 3);
        int base = kk * WPB + c4 * 2 + ((row >> 2) & 1);
        Wp[base + 0] = f2tf(v.x);
        Wp[base + 2] = f2tf(v.y);
        Wp[base + 4] = f2tf(v.z);
        Wp[base + 6] = f2tf(v.w);
    }
    __syncthreads();

    const int wid = tid >> 5, lane = tid & 31;
    const int g = lane >> 2, tig = lane & 3;
    const int wm = wid & 1, wn = wid >> 1;
    const int mbase = wm * 64, nbase = wn * 32;

    float c[4][4][4];
#pragma unroll
    for (int mt = 0; mt < 4; mt++)
#pragma unroll
        for (int nt = 0; nt < 4; nt++)
#pragma unroll
            for (int j = 0; j < 4; j++) c[mt][nt][j] = 0.f;

#pragma unroll
    for (int ks = 0; ks < 8; ks++) {
        unsigned a[4][4];
#pragma unroll
        for (int mt = 0; mt < 4; mt++) {
            int r = mbase + mt * 16 + g;
            float2 ap = *(const float2*)&Xs[r * XST + ks * 8 + tig * 2];
            float2 aq = *(const float2*)&Xs[(r + 8) * XST + ks * 8 + tig * 2];
            a[mt][0] = fu(ap.x); a[mt][1] = fu(aq.x);
            a[mt][2] = fu(ap.y); a[mt][3] = fu(aq.y);
        }
        unsigned b[4][2];
#pragma unroll
        for (int nt = 0; nt < 4; nt++) {
            int n = nbase + nt * 8 + g;
            float2 bp = *(const float2*)&Wp[(ks * 4 + tig) * WPB + n * 2];
            b[nt][0] = fu(bp.x); b[nt][1] = fu(bp.y);
        }
#pragma unroll
        for (int mt = 0; mt < 4; mt++)
#pragma unroll
            for (int nt = 0; nt < 4; nt++)
                mma8(c[mt][nt], a[mt][0], a[mt][1], a[mt][2], a[mt][3],
                     b[nt][0], b[nt][1]);
    }

    // epilogue: Bx partials (x read back from permuted Xs)
    float bv0[4], bv1[4];
    int pl[4];
#pragma unroll
    for (int nt = 0; nt < 4; nt++) {
        int d0 = nbase + nt * 8 + tig * 2;
        int dl = d0 & 63;
        pl[nt] = pmk(dl);                 // perm(dl); perm(dl+1) = perm(dl)+2
        bv0[nt] = bias[n0 + d0];
        bv1[nt] = bias[n0 + d0 + 1];
    }
#pragma unroll
    for (int mt = 0; mt < 4; mt++) {
        int r0 = mbase + mt * 16 + g;
        int r1 = r0 + 8;
        float p0 = 0.f, p1 = 0.f;
#pragma unroll
        for (int nt = 0; nt < 4; nt++) {
            float x00 = Xs[r0 * XST + pl[nt]];
            float x01 = Xs[r0 * XST + pl[nt] + 2];
            float x10 = Xs[r1 * XST + pl[nt]];
            float x11 = Xs[r1 * XST + pl[nt] + 2];
            p0 += (c[mt][nt][0] + bv0[nt]) * x00 + (c[mt][nt][1] + bv1[nt]) * x01;
            p1 += (c[mt][nt][2] + bv0[nt]) * x10 + (c[mt][nt][3] + bv1[nt]) * x11;
        }
        p0 += __shfl_xor_sync(0xffffffffu, p0, 1, 4);
        p0 += __shfl_xor_sync(0xffffffffu, p0, 2, 4);
        p1 += __shfl_xor_sync(0xffffffffu, p1, 1, 4);
        p1 += __shfl_xor_sync(0xffffffffu, p1, 2, 4);
        if (tig == 0) {
            red[r0 * 4 + wn] = p0;
            red[r1 * 4 + wn] = p1;
        }
    }
    __syncthreads();
    {
        int r = tid >> 1, grp = tid & 1;
        float bx = red[r * 4 + grp * 2] + red[r * 4 + grp * 2 + 1];
        int n_idx = blockIdx.y * 2 + grp;
        g_Bx[(long)(m0 + r) * DS + n_idx] = bx;
    }
}

// ---------------------------------------------------------------------------
// Kernel 1c: per-chunk P,v via binary tree combine (6 levels)
// ---------------------------------------------------------------------------
#define MSTRIDE 272
#define CK_BUFA 0
#define CK_BUFB (32 * MSTRIDE)
#define CK_VX   (2 * 32 * MSTRIDE)
#define CK_VA   (CK_VX + 64 * 16)
#define CK_VB   (CK_VA + 32 * 16)
#define CK_SMEM (CK_VB + 32 * 16)

__global__ __launch_bounds__(256) void k_chunk() {
    extern __shared__ float sm[];
    float* bufA = sm + CK_BUFA;
    float* bufB = sm + CK_BUFB;
    float* VX   = sm + CK_VX;
    float* Va   = sm + CK_VA;
    float* Vb   = sm + CK_VB;
    const int tid = threadIdx.x;
    const int bc = blockIdx.x;
    const long rowbase = (long)bc * CHUNK;

#pragma unroll
    for (int it = 0; it < 8; it++) {
        int i4 = it * 256 + tid;
        int m = i4 >> 6, e4 = (i4 & 63) * 4;
        *(float4*)&bufA[m * MSTRIDE + e4] =
            *(const float4*)&g_A[(rowbase + 2 * m) * 256 + e4];
    }
    *(float4*)&VX[tid * 4] = *(const float4*)&g_Bx[rowbase * DS + tid * 4];
    __syncthreads();

#pragma unroll
    for (int rep = 0; rep < 2; rep++) {
        int r = rep * 256 + tid;
        int m = r >> 4, i = r & 15;
        const float* arow = &g_A[(rowbase + 2 * m + 1) * 256 + i * 16];
        float4 a0 = *(const float4*)&arow[0];
        float4 a1 = *(const float4*)&arow[4];
        float4 a2 = *(const float4*)&arow[8];
        float4 a3 = *(const float4*)&arow[12];
        float av[16] = {a0.x, a0.y, a0.z, a0.w, a1.x, a1.y, a1.z, a1.w,
                        a2.x, a2.y, a2.z, a2.w, a3.x, a3.y, a3.z, a3.w};
        float acc[16];
#pragma unroll
        for (int l = 0; l < 16; l++) acc[l] = 0.f;
        float accv = VX[(2 * m + 1) * 16 + i];
#pragma unroll
        for (int q = 0; q < 16; q++) {
            float aq = av[q];
            float4 b0 = *(const float4*)&bufA[m * MSTRIDE + q * 16 + 0];
            float4 b1 = *(const float4*)&bufA[m * MSTRIDE + q * 16 + 4];
            float4 b2 = *(const float4*)&bufA[m * MSTRIDE + q * 16 + 8];
            float4 b3 = *(const float4*)&bufA[m * MSTRIDE + q * 16 + 12];
            acc[0]  += aq * b0.x; acc[1]  += aq * b0.y;
            acc[2]  += aq * b0.z; acc[3]  += aq * b0.w;
            acc[4]  += aq * b1.x; acc[5]  += aq * b1.y;
            acc[6]  += aq * b1.z; acc[7]  += aq * b1.w;
            acc[8]  += aq * b2.x; acc[9]  += aq * b2.y;
            acc[10] += aq * b2.z; acc[11] += aq * b2.w;
            acc[12] += aq * b3.x; acc[13] += aq * b3.y;
            acc[14] += aq * b3.z; acc[15] += aq * b3.w;
            accv += aq * VX[2 * m * 16 + q];
        }
#pragma unroll
        for (int l4 = 0; l4 < 4; l4++)
            *(float4*)&bufB[m * MSTRIDE + i * 16 + l4 * 4] =
                make_float4(acc[l4 * 4], acc[l4 * 4 + 1],
                            acc[l4 * 4 + 2], acc[l4 * 4 + 3]);
        Vb[m * 16 + i] = accv;
    }
    __syncthreads();

    float* src = bufB; float* dst = bufA;
    float* vs = Vb;    float* vd = Va;
#pragma unroll
    for (int lev = 1; lev <= 5; lev++) {
        int nmerge = 32 >> lev;
        int rows = nmerge * 16;
        if (tid < rows) {
            int m = tid >> 4, i = tid & 15;
            const float* a1p = &src[(2 * m + 1) * MSTRIDE + i * 16];
            float4 a0 = *(const float4*)&a1p[0];
            float4 a1 = *(const float4*)&a1p[4];
            float4 a2 = *(const float4*)&a1p[8];
            float4 a3 = *(const float4*)&a1p[12];
            float av[16] = {a0.x, a0.y, a0.z, a0.w, a1.x, a1.y, a1.z, a1.w,
                            a2.x, a2.y, a2.z, a2.w, a3.x, a3.y, a3.z, a3.w};
            float acc[16];
#pragma unroll
            for (int l = 0; l < 16; l++) acc[l] = 0.f;
            float accv = vs[(2 * m + 1) * 16 + i];
#pragma unroll
            for (int q = 0; q < 16; q++) {
                float aq = av[q];
                const float* bp = &src[2 * m * MSTRIDE + q * 16];
                float4 b0 = *(const float4*)&bp[0];
                float4 b1 = *(const float4*)&bp[4];
                float4 b2 = *(const float4*)&bp[8];
                float4 b3 = *(const float4*)&bp[12];
                acc[0]  += aq * b0.x; acc[1]  += aq * b0.y;
                acc[2]  += aq * b0.z; acc[3]  += aq * b0.w;
                acc[4]  += aq * b1.x; acc[5]  += aq * b1.y;
                acc[6]  += aq * b1.z; acc[7]  += aq * b1.w;
                acc[8]  += aq * b2.x; acc[9]  += aq * b2.y;
                acc[10] += aq * b2.z; acc[11] += aq * b2.w;
                acc[12] += aq * b3.x; acc[13] += aq * b3.y;
                acc[14] += aq * b3.z; acc[15] += aq * b3.w;
                accv += aq * vs[2 * m * 16 + q];
            }
#pragma unroll
            for (int l4 = 0; l4 < 4; l4++)
                *(float4*)&dst[m * MSTRIDE + i * 16 + l4 * 4] =
                    make_float4(acc[l4 * 4], acc[l4 * 4 + 1],
                                acc[l4 * 4 + 2], acc[l4 * 4 + 3]);
            vd[m * 16 + i] = accv;
        }
        __syncthreads();
        float* t = src; src = dst; dst = t;
        float* tv = vs; vs = vd; vd = tv;
    }

    g_P[(long)bc * 256 + tid] = src[tid];
    if (tid < 16) g_v[bc * DS + tid] = vs[tid];
}

// ---------------------------------------------------------------------------
// Kernel 1d: superchunk combine (tree over 8 chunk (P,v) -> (SP,Sv))
// ---------------------------------------------------------------------------
#define SST 260
__global__ __launch_bounds__(256) void k_super() {
    __shared__ float P[2][8 * SST];
    __shared__ float V[2][8 * 16];
    const int tid = threadIdx.x;
    const int bs = blockIdx.x;                  // b*NSUPER + s
    const long cbase = (long)bs * SCH;

#pragma unroll
    for (int e = 0; e < 8; e++) {
        int idx = e * 256 + tid;
        int m = idx >> 8, ij = idx & 255;
        P[0][m * SST + ij] = g_P[(cbase + m) * 256 + ij];
    }
    if (tid < 128) V[0][tid] = g_v[cbase * DS + tid];
    __syncthreads();

    int cur = 0;
#pragma unroll
    for (int lev = 0; lev < 3; lev++) {
        int nm = 4 >> lev;
        int elems = nm * 256;
#pragma unroll
        for (int e = 0; e < 4; e++) {
            int idx = e * 256 + tid;
            if (idx < elems) {
                int m = idx >> 8, ij = idx & 255;
                int i = ij >> 4, jj = ij & 15;
                const float* P1 = &P[cur][(2 * m + 1) * SST + i * 16];
                const float* P0 = &P[cur][2 * m * SST];
                float s = 0.f;
#pragma unroll
                for (int q = 0; q < 16; q++) s += P1[q] * P0[q * 16 + jj];
                P[cur ^ 1][m * SST + ij] = s;
                if (jj == 0) {
                    float sv = V[cur][(2 * m + 1) * 16 + i];
                    const float* V0 = &V[cur][2 * m * 16];
#pragma unroll
                    for (int q = 0; q < 16; q++) sv += P1[q] * V0[q];
                    V[cur ^ 1][m * 16 + i] = sv;
                }
            }
        }
        __syncthreads();
        cur ^= 1;
    }

    g_SP[(long)bs * 256 + tid] = P[cur][tid];
    if (tid < 16) g_Sv[bs * DS + tid] = V[cur][tid];
}

// ---------------------------------------------------------------------------
// Kernel 2: sequential scan over 8 superchunks per batch
// ---------------------------------------------------------------------------
__global__ __launch_bounds__(32) void k_scan2() {
    const int b = blockIdx.x;
    const int lane = threadIdx.x;
    const long base = (long)b * NSUPER;

    float h[16];
#pragma unroll
    for (int q = 0; q < 16; q++) h[q] = 0.f;
    float mine = 0.f;

    float4 p0 = {0,0,0,0}, p1 = p0, p2 = p0, p3 = p0;
    float v = 0.f;
    if (lane < 16) {
        const float* P = &g_SP[base * 256 + lane * 16];
        p0 = *(const float4*)&P[0];
        p1 = *(const float4*)&P[4];
        p2 = *(const float4*)&P[8];
        p3 = *(const float4*)&P[12];
        v = g_Sv[base * DS + lane];
    }

    for (int s = 0; s < NSUPER; s++) {
        float4 q0 = p0, q1 = p1, q2 = p2, q3 = p3;
        float vn = v;
        if (lane < 16 && s + 1 < NSUPER) {
            const float* Pn = &g_SP[(base + s + 1) * 256 + lane * 16];
            q0 = *(const float4*)&Pn[0];
            q1 = *(const float4*)&Pn[4];
            q2 = *(const float4*)&Pn[8];
            q3 = *(const float4*)&Pn[12];
            vn = g_Sv[(base + s + 1) * DS + lane];
        }
        float hn = 0.f;
        if (lane < 16) {
            g_sh0[(base + s) * DS + lane] = mine;
            float s0 = v + p0.x * h[0] + p0.y * h[1] + p0.z * h[2] + p0.w * h[3];
            float s1 = p1.x * h[4] + p1.y * h[5] + p1.z * h[6] + p1.w * h[7];
            float s2 = p2.x * h[8] + p2.y * h[9] + p2.z * h[10] + p2.w * h[11];
            float s3 = p3.x * h[12] + p3.y * h[13] + p3.z * h[14] + p3.w * h[15];
            hn = (s0 + s1) + (s2 + s3);
            mine = hn;
        }
#pragma unroll
        for (int q = 0; q < 16; q++)
            h[q] = __shfl_sync(0xffffffffu, hn, q);
        p0 = q0; p1 = q1; p2 = q2; p3 = q3; v = vn;
    }
}

// ---------------------------------------------------------------------------
// Kernel 2b (fused mid+replay): one block per (batch, super).
// ---------------------------------------------------------------------------
__global__ __launch_bounds__(256) void k_midreplay() {
    __shared__ float Ps[8 * SST];
    __shared__ float Vs[8 * 16];
    __shared__ float hcs[8 * 16];
    const int tid = threadIdx.x;
    const int bs = blockIdx.x;                   // b*NSUPER + s
    const long cbase = (long)bs * SCH;

#pragma unroll
    for (int e = 0; e < 8; e++) {
        int idx = e * 256 + tid;
        int m = idx >> 8, ij = idx & 255;
        Ps[m * SST + ij] = g_P[(cbase + m) * 256 + ij];
    }
    if (tid < 128) Vs[tid] = g_v[cbase * DS + tid];
    __syncthreads();

    if (tid < 32) {
        const int lane = tid;
        float hv = (lane < 16) ? g_sh0[bs * DS + lane] : 0.f;
        float h[16];
#pragma unroll
        for (int q = 0; q < 16; q++) h[q] = __shfl_sync(0xffffffffu, hv, q);
        for (int c = 0; c < SCH; c++) {
            if (lane < 16) hcs[c * 16 + lane] = h[lane];
            float hn = 0.f;
            if (lane < 16) {
                hn = Vs[c * 16 + lane];
#pragma unroll
                for (int q = 0; q < 16; q++)
                    hn += Ps[c * SST + lane * 16 + q] * h[q];
            }
#pragma unroll
            for (int q = 0; q < 16; q++)
                h[q] = __shfl_sync(0xffffffffu, hn, q);
        }
    }
    __syncthreads();

    {
        const int w = tid >> 5, lane = tid & 31;
        const long rowbase = (cbase + w) * CHUNK;

        float h[16];
#pragma unroll
        for (int q = 0; q < 16; q++) h[q] = hcs[w * 16 + q];

        float4 a0 = {0,0,0,0}, a1 = a0, a2 = a0, a3 = a0;
        float bx = 0.f;
        if (lane < 16) {
            const float* Arow = &g_A[rowbase * 256 + lane * 16];
            a0 = *(const float4*)&Arow[0];
            a1 = *(const float4*)&Arow[4];
            a2 = *(const float4*)&Arow[8];
            a3 = *(const float4*)&Arow[12];
            bx = g_Bx[rowbase * DS + lane];
        }
        for (int t = 0; t < CHUNK; t++) {
            float4 n0 = a0, n1 = a1, n2 = a2, n3 = a3;
            float bxn = bx;
            if (lane < 16 && t + 1 < CHUNK) {
                const float* An = &g_A[(rowbase + t + 1) * 256 + lane * 16];
                n0 = *(const float4*)&An[0];
                n1 = *(const float4*)&An[4];
                n2 = *(const float4*)&An[8];
                n3 = *(const float4*)&An[12];
                bxn = g_Bx[(rowbase + t + 1) * DS + lane];
            }
            float hn = 0.f;
            if (lane < 16) {
                float s0 = bx + a0.x * h[0] + a0.y * h[1] + a0.z * h[2] + a0.w * h[3];
                float s1 = a1.x * h[4] + a1.y * h[5] + a1.z * h[6] + a1.w * h[7];
                float s2 = a2.x * h[8] + a2.y * h[9] + a2.z * h[10] + a2.w * h[11];
                float s3 = a3.x * h[12] + a3.y * h[13] + a3.z * h[14] + a3.w * h[15];
                hn = (s0 + s1) + (s2 + s3);
                g_H[(rowbase + t) * DS + lane] = hn;
            }
#pragma unroll
            for (int q = 0; q < 16; q++)
                h[q] = __shfl_sync(0xffffffffu, hn, q);
            a0 = n0; a1 = n1; a2 = n2; a3 = n3; bx = bxn;
        }
    }
}

// ---------------------------------------------------------------------------
// Kernel 3 (tensor): out[m,d] = sum_n h[m,n] * (x @ W_C[:,n,:])[m,d] + h @ b_C'
// Paired smem layouts; W register-prefetched per n.
// ---------------------------------------------------------------------------
#define KC_WS   (128 * XST)
#define KC_HS   (KC_WS + 32 * WPA)
#define KC_SMEM (KC_HS + 128 * 17)

__global__ __launch_bounds__(256) void k_outC(const float* __restrict__ x,
                                              const float* __restrict__ W_C,
                                              const float* __restrict__ b_C,
                                              float* __restrict__ out) {
    extern __shared__ float sm[];
    float* Xs = sm;             // [128][XST] perm cols
    float* Wp = sm + KC_WS;     // [32][WPA] k-pair rows (reused raw for b_C)
    float* Hs = sm + KC_HS;     // [128][17] fp32 h
    const int tid = threadIdx.x;
    const int m0 = blockIdx.x * 128;

#pragma unroll
    for (int it = 0; it < 8; it++) {
        int i4 = it * 256 + tid;
        int row = i4 >> 4, c4 = (i4 & 15) * 4;
        float4 v = *(const float4*)&x[(long)(m0 + row) * 64 + c4];
        int base = row * XST + ((c4 >> 3) << 3) + ((c4 >> 2) & 1);
        Xs[base + 0] = f2tf(v.x);
        Xs[base + 2] = f2tf(v.y);
        Xs[base + 4] = f2tf(v.z);
        Xs[base + 6] = f2tf(v.w);
    }
#pragma unroll
    for (int it = 0; it < 2; it++) {
        int i4 = it * 256 + tid;
        int row = i4 >> 2, c4 = (i4 & 3) * 4;
        float4 v = *(const float4*)&g_H[(long)(m0 + row) * DS + c4];
        Hs[row * 17 + c4 + 0] = v.x;
        Hs[row * 17 + c4 + 1] = v.y;
        Hs[row * 17 + c4 + 2] = v.z;
        Hs[row * 17 + c4 + 3] = v.w;
    }

    int wkk[4], wsl[4], wd[4];
#pragma unroll
    for (int it = 0; it < 4; it++) {
        int i4 = it * 256 + tid;
        int k = i4 >> 4;
        wkk[it] = ((k >> 3) << 2) + (k & 3);
        wsl[it] = (k >> 2) & 1;
        wd[it] = (i4 & 15) * 4;
    }
    int wkrow[4];
#pragma unroll
    for (int it = 0; it < 4; it++) wkrow[it] = (it * 256 + tid) >> 4;
    float4 wreg[4];
#pragma unroll
    for (int it = 0; it < 4; it++)
        wreg[it] = *(const float4*)&W_C[(long)wkrow[it] * 1024 + wd[it]];   // n=0

    const int wid = tid >> 5, lane = tid & 31;
    const int g = lane >> 2, tig = lane & 3;
    const int wm = wid & 3, wn = wid >> 2;
    const int mbase = wm * 32, nbase = wn * 32;

    float oacc[2][4][4];
#pragma unroll
    for (int mt = 0; mt < 2; mt++)
#pragma unroll
        for (int nt = 0; nt < 4; nt++)
#pragma unroll
            for (int j = 0; j < 4; j++) oacc[mt][nt][j] = 0.f;

    for (int n = 0; n < 16; n++) {
        __syncthreads();
#pragma unroll
        for (int it = 0; it < 4; it++) {
            int base = wkk[it] * WPA + wd[it] * 2 + wsl[it];
            Wp[base + 0] = f2tf(wreg[it].x);
            Wp[base + 2] = f2tf(wreg[it].y);
            Wp[base + 4] = f2tf(wreg[it].z);
            Wp[base + 6] = f2tf(wreg[it].w);
        }
        __syncthreads();
        if (n + 1 < 16) {
#pragma unroll
            for (int it = 0; it < 4; it++)
                wreg[it] = *(const float4*)
                    &W_C[(long)wkrow[it] * 1024 + (n + 1) * 64 + wd[it]];
        }

        float c[2][4][4];
#pragma unroll
        for (int mt = 0; mt < 2; mt++)
#pragma unroll
            for (int nt = 0; nt < 4; nt++)
#pragma unroll
                for (int j = 0; j < 4; j++) c[mt][nt][j] = 0.f;

#pragma unroll
        for (int ks = 0; ks < 8; ks++) {
            unsigned a[2][4];
#pragma unroll
            for (int mt = 0; mt < 2; mt++) {
                int r = mbase + mt * 16 + g;
                float2 ap = *(const float2*)&Xs[r * XST + ks * 8 + tig * 2];
                float2 aq = *(const float2*)&Xs[(r + 8) * XST + ks * 8 + tig * 2];
                a[mt][0] = fu(ap.x); a[mt][1] = fu(aq.x);
                a[mt][2] = fu(ap.y); a[mt][3] = fu(aq.y);
            }
            unsigned b[4][2];
#pragma unroll
            for (int nt = 0; nt < 4; nt++) {
                int nn = nbase + nt * 8 + g;
                float2 bp = *(const float2*)&Wp[(ks * 4 + tig) * WPA + nn * 2];
                b[nt][0] = fu(bp.x); b[nt][1] = fu(bp.y);
            }
#pragma unroll
            for (int mt = 0; mt < 2; mt++)
#pragma unroll
                for (int nt = 0; nt < 4; nt++)
                    mma8(c[mt][nt], a[mt][0], a[mt][1], a[mt][2], a[mt][3],
                         b[nt][0], b[nt][1]);
        }

#pragma unroll
        for (int mt = 0; mt < 2; mt++) {
            int r0 = mbase + mt * 16 + g;
            float ha = Hs[r0 * 17 + n];
            float hb = Hs[(r0 + 8) * 17 + n];
#pragma unroll
            for (int nt = 0; nt < 4; nt++) {
                oacc[mt][nt][0] += ha * c[mt][nt][0];
                oacc[mt][nt][1] += ha * c[mt][nt][1];
                oacc[mt][nt][2] += hb * c[mt][nt][2];
                oacc[mt][nt][3] += hb * c[mt][nt][3];
            }
        }
    }

    // bias epilogue: plain 68-stride layout in the Wp buffer
    __syncthreads();
    {
        int nn = tid >> 4, c4 = (tid & 15) * 4;
        float4 v = *(const float4*)&b_C[nn * 64 + c4];
        Wp[nn * 68 + c4 + 0] = v.x;
        Wp[nn * 68 + c4 + 1] = v.y;
        Wp[nn * 68 + c4 + 2] = v.z;
        Wp[nn * 68 + c4 + 3] = v.w;
    }
    __syncthreads();

#pragma unroll
    for (int mt = 0; mt < 2; mt++) {
        int r0 = mbase + mt * 16 + g;
        int r1 = r0 + 8;
#pragma unroll
        for (int nt = 0; nt < 4; nt++) {
            int col = nbase + nt * 8 + tig * 2;
            float s00 = 0.f, s01 = 0.f, s10 = 0.f, s11 = 0.f;
#pragma unroll
            for (int nn = 0; nn < 16; nn++) {
                float ha = Hs[r0 * 17 + nn], hb = Hs[r1 * 17 + nn];
                float w0 = Wp[nn * 68 + col], w1 = Wp[nn * 68 + col + 1];
                s00 += ha * w0; s01 += ha * w1;
                s10 += hb * w0; s11 += hb * w1;
            }
            *(float2*)&out[(long)(m0 + r0) * 64 + col] =
                make_float2(oacc[mt][nt][0] + s00, oacc[mt][nt][1] + s01);
            *(float2*)&out[(long)(m0 + r1) * 64 + col] =
                make_float2(oacc[mt][nt][2] + s10, oacc[mt][nt][3] + s11);
        }
    }
}

// ---------------------------------------------------------------------------
extern "C" void kernel_launch(void* const* d_in, const int* in_sizes, int n_in,
                              void* d_out, int out_size) {
    const float* x   = (const float*)d_in[0];
    const float* W_A = (const float*)d_in[1];
    const float* b_A = (const float*)d_in[2];
    const float* W_B = (const float*)d_in[3];
    const float* b_B = (const float*)d_in[4];
    const float* W_C = (const float*)d_in[5];
    const float* b_C = (const float*)d_in[6];
    float* out = (float*)d_out;

    const int smA = (128 * XST + 32 * WPA) * sizeof(float);
    const int smB = (128 * XST + 32 * WPB + 512) * sizeof(float);
    const int smC = CK_SMEM * sizeof(float);
    const int smO = KC_SMEM * sizeof(float);
    cudaFuncSetAttribute(k_projA, cudaFuncAttributeMaxDynamicSharedMemorySize, smA);
    cudaFuncSetAttribute(k_projB, cudaFuncAttributeMaxDynamicSharedMemorySize, smB);
    cudaFuncSetAttribute(k_chunk, cudaFuncAttributeMaxDynamicSharedMemorySize, smC);
    cudaFuncSetAttribute(k_outC,  cudaFuncAttributeMaxDynamicSharedMemorySize, smO);

    k_projA<<<dim3(ROWS / 128, 4), 256, smA>>>(x, W_A, b_A);
    k_projB<<<dim3(ROWS / 128, 8), 256, smB>>>(x, W_B, b_B);
    k_chunk<<<BATCH * NCHUNK, 256, smC>>>();
    k_super<<<BATCH * NSUPER, 256>>>();
    k_scan2<<<BATCH, 32>>>();
    k_midreplay<<<BATCH * NSUPER, 256>>>();
    k_outC<<<ROWS / 128, 256, smO>>>(x, W_C, b_C, out);
}